// round 11
// baseline (speedup 1.0000x reference)
#include <cuda_runtime.h>

// Problem constants (fixed shapes)
#define NN      50000
#define CC      32
#define HH      32
#define EE      1600000      // == NN*CC (exploited in prep)
#define NH      1600000
#define NH4     400000
#define FC      64
#define NCLS    2
#define BN_EPS  1e-5f

#define TILES   196          // ceil(NN/256)
#define CNTSZ   (TILES * 256)
#define GGRID   6250         // gather: NN/8 warps-per-block
#define VGRID   592          // gemv grid (4 per SM)
#define VCHUNKS 6250         // NH4 / 64

// Scratch (device globals; all zero at module load)
__device__ __align__(16) float g_xbn[NN * CC];
__device__ __align__(16) float g_y[NN * HH];
__device__ __align__(16) float g_res[NN * HH];   // relu'd gather result
__device__ __align__(16) uint2 g_edges[EE];
__device__ unsigned g_cnt[CNTSZ];       // dst histogram (zeroed by gemv tail)
__device__ unsigned g_rowloc[CNTSZ];    // per-tile-local exclusive offsets
__device__ unsigned g_cursor[NN];
__device__ unsigned g_bsum[256];
__device__ unsigned g_tileoff[256];
__device__ float g_hacc[FC];            // zeroed by gemv tail
__device__ unsigned g_sem;              // zeroed by gemv tail
__device__ unsigned g_scansem;          // zeroed by scan tail

// ---------------------------------------------------------------------------
// Kernel 1: BN + projection y = bn(x) @ (W1+W2) + dst histogram
// ---------------------------------------------------------------------------
__global__ __launch_bounds__(256)
void prep_kernel(const float* __restrict__ x,
                 const float* __restrict__ gamma,
                 const float* __restrict__ beta,
                 const float* __restrict__ mean,
                 const float* __restrict__ var,
                 const float* __restrict__ W,
                 const int*   __restrict__ edge_index) {
    __shared__ float sWs[CC * HH];
    for (int i = threadIdx.x; i < CC * HH; i += 256)
        sWs[i] = W[CC * HH + i] + W[2 * CC * HH + i];
    __syncthreads();

    int i = blockIdx.x * 256 + threadIdx.x;       // exactly 1.6M threads
    int lane = i & 31;

    // histogram (thread i handles edge i; EE == NN*CC)
    atomicAdd(&g_cnt[edge_index[EE + i]], 1u);

    float xv = x[i];
    float s = rsqrtf(var[lane] + BN_EPS) * gamma[lane];
    float xb = (xv - mean[lane]) * s + beta[lane];
    g_xbn[i] = xb;

    float y0 = 0.f, y1 = 0.f, y2 = 0.f, y3 = 0.f;
#pragma unroll
    for (int c = 0; c < CC; c += 4) {
        y0 = fmaf(__shfl_sync(0xffffffffu, xb, c    ), sWs[(c    ) * HH + lane], y0);
        y1 = fmaf(__shfl_sync(0xffffffffu, xb, c + 1), sWs[(c + 1) * HH + lane], y1);
        y2 = fmaf(__shfl_sync(0xffffffffu, xb, c + 2), sWs[(c + 2) * HH + lane], y2);
        y3 = fmaf(__shfl_sync(0xffffffffu, xb, c + 3), sWs[(c + 3) * HH + lane], y3);
    }
    g_y[i] = (y0 + y1) + (y2 + y3);
}

// ---------------------------------------------------------------------------
// Kernel 2: fused scan — per-tile exclusive scan, then last block scans tiles
// ---------------------------------------------------------------------------
__global__ void scan_kernel() {
    __shared__ unsigned a[256], b[256];
    int idx = blockIdx.x * 256 + threadIdx.x;
    unsigned v = g_cnt[idx];
    a[threadIdx.x] = v;
    __syncthreads();
    unsigned* s = a; unsigned* d = b;
    for (int o = 1; o < 256; o <<= 1) {
        unsigned t = s[threadIdx.x];
        if (threadIdx.x >= o) t += s[threadIdx.x - o];
        d[threadIdx.x] = t;
        __syncthreads();
        unsigned* tmp = s; s = d; d = tmp;
    }
    unsigned excl = s[threadIdx.x] - v;
    g_rowloc[idx] = excl;
    if (idx < NN) g_cursor[idx] = excl;
    if (threadIdx.x == 255) g_bsum[blockIdx.x] = s[255];

    __shared__ bool isLast;
    __syncthreads();
    if (threadIdx.x == 0) {
        __threadfence();
        isLast = (atomicAdd(&g_scansem, 1u) == (unsigned)(TILES - 1));
    }
    __syncthreads();
    if (isLast) {
        __threadfence();
        unsigned w = (threadIdx.x < TILES) ? g_bsum[threadIdx.x] : 0u;
        a[threadIdx.x] = w;
        __syncthreads();
        s = a; d = b;
        for (int o = 1; o < 256; o <<= 1) {
            unsigned t = s[threadIdx.x];
            if (threadIdx.x >= o) t += s[threadIdx.x - o];
            d[threadIdx.x] = t;
            __syncthreads();
            unsigned* tmp = s; s = d; d = tmp;
        }
        g_tileoff[threadIdx.x] = s[threadIdx.x] - w;
        if (threadIdx.x == 0) g_scansem = 0u;
    }
}

// ---------------------------------------------------------------------------
// Kernel 3: reorder edges into dst buckets (4 edges per thread for atomic MLP)
// ---------------------------------------------------------------------------
#define QE (EE / 4)
__global__ __launch_bounds__(256)
void reorder_kernel(const int* __restrict__ edge_index,
                    const float* __restrict__ edge_weight) {
    int e = blockIdx.x * blockDim.x + threadIdx.x;
    if (e >= QE) return;

    int s0 = edge_index[e];
    int s1 = edge_index[e + QE];
    int s2 = edge_index[e + 2 * QE];
    int s3 = edge_index[e + 3 * QE];
    int d0 = edge_index[EE + e];
    int d1 = edge_index[EE + e + QE];
    int d2 = edge_index[EE + e + 2 * QE];
    int d3 = edge_index[EE + e + 3 * QE];
    float w0 = edge_weight[e];
    float w1 = edge_weight[e + QE];
    float w2 = edge_weight[e + 2 * QE];
    float w3 = edge_weight[e + 3 * QE];

    unsigned p0 = g_tileoff[d0 >> 8] + atomicAdd(&g_cursor[d0], 1u);
    unsigned p1 = g_tileoff[d1 >> 8] + atomicAdd(&g_cursor[d1], 1u);
    unsigned p2 = g_tileoff[d2 >> 8] + atomicAdd(&g_cursor[d2], 1u);
    unsigned p3 = g_tileoff[d3 >> 8] + atomicAdd(&g_cursor[d3], 1u);
    g_edges[p0] = make_uint2((unsigned)s0, __float_as_uint(w0));
    g_edges[p1] = make_uint2((unsigned)s1, __float_as_uint(w1));
    g_edges[p2] = make_uint2((unsigned)s2, __float_as_uint(w2));
    g_edges[p3] = make_uint2((unsigned)s3, __float_as_uint(w3));
}

__device__ __forceinline__ unsigned row_start(int m) {
    return g_tileoff[m >> 8] + g_rowloc[m];
}

// ---------------------------------------------------------------------------
// Kernel 4: standalone CSR gather — warp per node, latency hidden by occupancy
// ---------------------------------------------------------------------------
__global__ __launch_bounds__(256)
void gather_kernel(const float* __restrict__ W) {   // W[0] block for self-loops
    __shared__ float sW0[CC * HH];
    for (int i = threadIdx.x; i < CC * HH; i += 256) sW0[i] = W[i];
    __syncthreads();

    const int lane = threadIdx.x & 31;
    const int n = blockIdx.x * 8 + (threadIdx.x >> 5);
    if (n >= NN) return;

    unsigned beg = row_start(n);
    unsigned end = row_start(n + 1);

    float ra = 0.f, rb = 0.f;
    for (unsigned j = beg; j < end; j += 32) {
        bool inr = (j + (unsigned)lane < end);
        uint2 ed = inr ? g_edges[j + lane] : make_uint2(0u, 0u);
        float wgt = inr ? __uint_as_float(ed.y) : 0.f;

        unsigned slm = __ballot_sync(0xffffffffu, inr && ed.x == (unsigned)n);
        if (slm) {    // rare self-loop(s): k=0 identity term, weight 1 each
            float cnt = (float)__popc(slm);
            float xc = g_xbn[(size_t)n * CC + lane];
            float s0 = 0.f;
#pragma unroll
            for (int c = 0; c < CC; c++)
                s0 = fmaf(__shfl_sync(0xffffffffu, xc, c), sW0[c * HH + lane], s0);
            ra = fmaf(cnt, s0, ra);
        }
#pragma unroll
        for (int i = 0; i < 32; i += 2) {
            float    wa = __shfl_sync(0xffffffffu, wgt, i);
            unsigned sa = __shfl_sync(0xffffffffu, ed.x, i);
            float    wb = __shfl_sync(0xffffffffu, wgt, i + 1);
            unsigned sb = __shfl_sync(0xffffffffu, ed.x, i + 1);
            ra = fmaf(wa, g_y[(size_t)sa * HH + lane], ra);
            rb = fmaf(wb, g_y[(size_t)sb * HH + lane], rb);
        }
    }
    g_res[(size_t)n * HH + lane] = fmaxf(ra + rb, 0.f);   // relu here
}

// ---------------------------------------------------------------------------
// Kernel 5: pure streaming GEMV h[f] = sum res4[i].W4[f,i] + fused head
// warp w: f-group (w&3)*16..+16, slot-half (w>>2)*32+lane.
// Per block-iteration: 64 float4 slots x 64 f = 64KB of fc1_w.
// ---------------------------------------------------------------------------
__global__ __launch_bounds__(256, 4)
void gemv_head_kernel(const float* __restrict__ fc1_w,
                      const float* __restrict__ fc1_b,
                      const float* __restrict__ fc2_w,
                      const float* __restrict__ fc2_b,
                      float* __restrict__ out) {
    const float4* R4 = reinterpret_cast<const float4*>(g_res);
    const float4* W4 = reinterpret_cast<const float4*>(fc1_w);

    const int tid  = threadIdx.x;
    const int w    = tid >> 5;
    const int lane = tid & 31;
    const int fg   = (w & 3) * 16;          // f-group base
    const int sh   = (w >> 2) * 32 + lane;  // slot within 64-slot chunk

    // zero histogram for the NEXT replay
    for (int idx = blockIdx.x * 256 + tid; idx < CNTSZ; idx += VGRID * 256)
        g_cnt[idx] = 0u;

    float acc[16];
#pragma unroll
    for (int k = 0; k < 16; k++) acc[k] = 0.f;

    for (int chunk = blockIdx.x; chunk < VCHUNKS; chunk += VGRID) {
        size_t slot = (size_t)chunk * 64 + sh;
        float4 rv = __ldg(R4 + slot);
#pragma unroll
        for (int k = 0; k < 16; k++) {
            float4 wv = __ldcs(W4 + (size_t)(fg + k) * NH4 + slot);
            acc[k] = fmaf(rv.x, wv.x, acc[k]);
            acc[k] = fmaf(rv.y, wv.y, acc[k]);
            acc[k] = fmaf(rv.z, wv.z, acc[k]);
            acc[k] = fmaf(rv.w, wv.w, acc[k]);
        }
    }

    // reduce: warp-reduce, then the 2 warps sharing each f-group combine in smem
    __shared__ float sAcc[FC];
    if (tid < FC) sAcc[tid] = 0.f;
    __syncthreads();
#pragma unroll
    for (int k = 0; k < 16; k++) {
        float v = acc[k];
        v += __shfl_xor_sync(0xffffffffu, v, 16);
        v += __shfl_xor_sync(0xffffffffu, v, 8);
        v += __shfl_xor_sync(0xffffffffu, v, 4);
        v += __shfl_xor_sync(0xffffffffu, v, 2);
        v += __shfl_xor_sync(0xffffffffu, v, 1);
        if (lane == 0) atomicAdd(&sAcc[fg + k], v);
    }
    __syncthreads();
    if (tid < FC) atomicAdd(&g_hacc[tid], sAcc[tid]);
    __syncthreads();

    // last block: head + cleanup
    __shared__ bool isLast;
    if (tid == 0) {
        __threadfence();
        isLast = (atomicAdd(&g_sem, 1u) == (unsigned)(VGRID - 1));
    }
    __syncthreads();
    if (isLast) {
        __threadfence();
        __shared__ float hv[FC];
        volatile float* vh = g_hacc;
        if (tid < FC) hv[tid] = fmaxf(vh[tid] + fc1_b[tid], 0.f);
        __syncthreads();
        if (tid < NCLS) {
            float s = fc2_b[tid];
#pragma unroll
            for (int f = 0; f < FC; f++)
                s = fmaf(hv[f], fc2_w[tid * FC + f], s);
            out[tid] = s;
        }
        __syncthreads();
        if (tid < FC) g_hacc[tid] = 0.f;
        if (tid == 0) g_sem = 0u;
    }
}

// ---------------------------------------------------------------------------
// launch
// ---------------------------------------------------------------------------
extern "C" void kernel_launch(void* const* d_in, const int* in_sizes, int n_in,
                              void* d_out, int out_size) {
    const float* x        = (const float*)d_in[0];
    const float* ew       = (const float*)d_in[1];
    const float* W        = (const float*)d_in[2];
    const float* bn_gamma = (const float*)d_in[3];
    const float* bn_beta  = (const float*)d_in[4];
    const float* bn_mean  = (const float*)d_in[5];
    const float* bn_var   = (const float*)d_in[6];
    const float* fc1_w    = (const float*)d_in[7];
    const float* fc1_b    = (const float*)d_in[8];
    const float* fc2_w    = (const float*)d_in[9];
    const float* fc2_b    = (const float*)d_in[10];
    const int*   ei       = (const int*)d_in[11];
    float* out            = (float*)d_out;

    prep_kernel<<<(NN * CC) / 256, 256>>>(x, bn_gamma, bn_beta, bn_mean, bn_var, W, ei);
    scan_kernel<<<TILES, 256>>>();
    reorder_kernel<<<(QE + 255) / 256, 256>>>(ei, ew);
    gather_kernel<<<GGRID, 256>>>(W);
    gemv_head_kernel<<<VGRID, 256>>>(fc1_w, fc1_b, fc2_w, fc2_b, out);
}

// round 12
// speedup vs baseline: 1.2274x; 1.2274x over previous
#include <cuda_runtime.h>

// Problem constants (fixed shapes)
#define NN      50000
#define CC      32
#define HH      32
#define EE      1600000      // == NN*CC (exploited in prep)
#define NH      1600000
#define NH4     400000
#define FC      64
#define NCLS    2
#define BN_EPS  1e-5f

#define TILES   196          // ceil(NN/256)
#define CNTSZ   (TILES * 256)
#define NPB     88           // nodes per block (multiple of 8)
#define FGRID   569          // ceil(NN/NPB)
#define FBLK    128          // fused kernel block size

// Scratch (device globals; all zero at module load)
__device__ __align__(16) float g_xbn[NN * CC];
__device__ __align__(16) float g_y[NN * HH];
__device__ __align__(16) uint2 g_edges[EE];
__device__ unsigned g_cnt[CNTSZ];       // dst histogram (zeroed by fused tail)
__device__ unsigned g_rowloc[CNTSZ];    // per-tile-local exclusive offsets
__device__ unsigned g_cursor[NN];
__device__ unsigned g_bsum[256];
__device__ unsigned g_tileoff[256];
__device__ float g_hacc[FC];            // zeroed by fused tail
__device__ unsigned g_sem;              // zeroed by fused tail
__device__ unsigned g_scansem;          // zeroed by scan tail

// ---------------------------------------------------------------------------
// Kernel 1: BN + projection y = bn(x) @ (W1+W2) + dst histogram
// ---------------------------------------------------------------------------
__global__ __launch_bounds__(256)
void prep_kernel(const float* __restrict__ x,
                 const float* __restrict__ gamma,
                 const float* __restrict__ beta,
                 const float* __restrict__ mean,
                 const float* __restrict__ var,
                 const float* __restrict__ W,
                 const int*   __restrict__ edge_index) {
    __shared__ float sWs[CC * HH];
    for (int i = threadIdx.x; i < CC * HH; i += 256)
        sWs[i] = W[CC * HH + i] + W[2 * CC * HH + i];
    __syncthreads();

    int i = blockIdx.x * 256 + threadIdx.x;       // exactly 1.6M threads
    int lane = i & 31;

    // histogram (thread i handles edge i; EE == NN*CC)
    atomicAdd(&g_cnt[edge_index[EE + i]], 1u);

    float xv = x[i];
    float s = rsqrtf(var[lane] + BN_EPS) * gamma[lane];
    float xb = (xv - mean[lane]) * s + beta[lane];
    g_xbn[i] = xb;

    float y0 = 0.f, y1 = 0.f, y2 = 0.f, y3 = 0.f;
#pragma unroll
    for (int c = 0; c < CC; c += 4) {
        y0 = fmaf(__shfl_sync(0xffffffffu, xb, c    ), sWs[(c    ) * HH + lane], y0);
        y1 = fmaf(__shfl_sync(0xffffffffu, xb, c + 1), sWs[(c + 1) * HH + lane], y1);
        y2 = fmaf(__shfl_sync(0xffffffffu, xb, c + 2), sWs[(c + 2) * HH + lane], y2);
        y3 = fmaf(__shfl_sync(0xffffffffu, xb, c + 3), sWs[(c + 3) * HH + lane], y3);
    }
    g_y[i] = (y0 + y1) + (y2 + y3);
}

// ---------------------------------------------------------------------------
// Kernel 2: fused scan — per-tile exclusive scan, then last block scans tiles
// ---------------------------------------------------------------------------
__global__ void scan_kernel() {
    __shared__ unsigned a[256], b[256];
    int idx = blockIdx.x * 256 + threadIdx.x;
    unsigned v = g_cnt[idx];
    a[threadIdx.x] = v;
    __syncthreads();
    unsigned* s = a; unsigned* d = b;
    for (int o = 1; o < 256; o <<= 1) {
        unsigned t = s[threadIdx.x];
        if (threadIdx.x >= o) t += s[threadIdx.x - o];
        d[threadIdx.x] = t;
        __syncthreads();
        unsigned* tmp = s; s = d; d = tmp;
    }
    unsigned excl = s[threadIdx.x] - v;
    g_rowloc[idx] = excl;
    if (idx < NN) g_cursor[idx] = excl;
    if (threadIdx.x == 255) g_bsum[blockIdx.x] = s[255];

    __shared__ bool isLast;
    __syncthreads();
    if (threadIdx.x == 0) {
        __threadfence();
        isLast = (atomicAdd(&g_scansem, 1u) == (unsigned)(TILES - 1));
    }
    __syncthreads();
    if (isLast) {
        __threadfence();
        unsigned w = (threadIdx.x < TILES) ? g_bsum[threadIdx.x] : 0u;
        a[threadIdx.x] = w;
        __syncthreads();
        s = a; d = b;
        for (int o = 1; o < 256; o <<= 1) {
            unsigned t = s[threadIdx.x];
            if (threadIdx.x >= o) t += s[threadIdx.x - o];
            d[threadIdx.x] = t;
            __syncthreads();
            unsigned* tmp = s; s = d; d = tmp;
        }
        g_tileoff[threadIdx.x] = s[threadIdx.x] - w;
        if (threadIdx.x == 0) g_scansem = 0u;
    }
}

// ---------------------------------------------------------------------------
// Kernel 3: reorder edges into dst buckets (4 edges per thread for atomic MLP)
// ---------------------------------------------------------------------------
#define QE (EE / 4)
__global__ __launch_bounds__(256)
void reorder_kernel(const int* __restrict__ edge_index,
                    const float* __restrict__ edge_weight) {
    int e = blockIdx.x * blockDim.x + threadIdx.x;
    if (e >= QE) return;

    int s0 = edge_index[e];
    int s1 = edge_index[e + QE];
    int s2 = edge_index[e + 2 * QE];
    int s3 = edge_index[e + 3 * QE];
    int d0 = edge_index[EE + e];
    int d1 = edge_index[EE + e + QE];
    int d2 = edge_index[EE + e + 2 * QE];
    int d3 = edge_index[EE + e + 3 * QE];
    float w0 = edge_weight[e];
    float w1 = edge_weight[e + QE];
    float w2 = edge_weight[e + 2 * QE];
    float w3 = edge_weight[e + 3 * QE];

    unsigned p0 = g_tileoff[d0 >> 8] + atomicAdd(&g_cursor[d0], 1u);
    unsigned p1 = g_tileoff[d1 >> 8] + atomicAdd(&g_cursor[d1], 1u);
    unsigned p2 = g_tileoff[d2 >> 8] + atomicAdd(&g_cursor[d2], 1u);
    unsigned p3 = g_tileoff[d3 >> 8] + atomicAdd(&g_cursor[d3], 1u);
    g_edges[p0] = make_uint2((unsigned)s0, __float_as_uint(w0));
    g_edges[p1] = make_uint2((unsigned)s1, __float_as_uint(w1));
    g_edges[p2] = make_uint2((unsigned)s2, __float_as_uint(w2));
    g_edges[p3] = make_uint2((unsigned)s3, __float_as_uint(w3));
}

__device__ __forceinline__ unsigned row_start(int m) {
    return g_tileoff[m >> 8] + g_rowloc[m];
}

// ---------------------------------------------------------------------------
// float4 group-gather of two nodes.
// Warp split into 4 groups of 8 lanes: group gid handles edge i+gid; lane q
// of a group loads float4 (channels 4q..4q+3). 4 independent load chains.
// Returns per-lane float4 of channels 4q..4q+3 (valid on all lanes after the
// butterfly reduction), relu applied.
// ---------------------------------------------------------------------------
__device__ __forceinline__ void gather2_f4(int n0, int n1, int nmax,
                                           const float4* sW04,
                                           float4& o0, float4& o1) {
    const int lane = threadIdx.x & 31;
    const int gid  = lane >> 3;       // edge group 0..3
    const int q    = lane & 7;        // float4 slot (channels 4q..4q+3)
    const float4* Y4 = reinterpret_cast<const float4*>(g_y);

    unsigned j0 = 0, e0 = 0, j1 = 0, e1 = 0;
    if (n0 < nmax) { j0 = row_start(n0); e0 = row_start(n0 + 1); }
    if (n1 < nmax) { j1 = row_start(n1); e1 = row_start(n1 + 1); }

    float4 a0 = make_float4(0.f, 0.f, 0.f, 0.f);
    float4 a1 = make_float4(0.f, 0.f, 0.f, 0.f);

    while (j0 < e0 || j1 < e1) {
        bool in0 = (j0 + (unsigned)lane < e0);
        bool in1 = (j1 + (unsigned)lane < e1);
        uint2 ed0 = in0 ? g_edges[j0 + lane] : make_uint2(0u, 0u);
        uint2 ed1 = in1 ? g_edges[j1 + lane] : make_uint2(0u, 0u);
        float w0v = in0 ? __uint_as_float(ed0.y) : 0.f;
        float w1v = in1 ? __uint_as_float(ed1.y) : 0.f;

        // rare self-loop(s): k=0 identity term, weight 1 each; group 0 adds
        unsigned sl0 = __ballot_sync(0xffffffffu, in0 && ed0.x == (unsigned)n0);
        unsigned sl1 = __ballot_sync(0xffffffffu, in1 && ed1.x == (unsigned)n1);
        if (sl0) {
            float cnt = (float)__popc(sl0);
            float xc = g_xbn[(size_t)n0 * CC + lane];
            float4 t = make_float4(0.f, 0.f, 0.f, 0.f);
#pragma unroll
            for (int c = 0; c < CC; c++) {
                float xb = __shfl_sync(0xffffffffu, xc, c);
                float4 wv = sW04[c * 8 + q];
                t.x = fmaf(xb, wv.x, t.x); t.y = fmaf(xb, wv.y, t.y);
                t.z = fmaf(xb, wv.z, t.z); t.w = fmaf(xb, wv.w, t.w);
            }
            if (gid == 0) {
                a0.x = fmaf(cnt, t.x, a0.x); a0.y = fmaf(cnt, t.y, a0.y);
                a0.z = fmaf(cnt, t.z, a0.z); a0.w = fmaf(cnt, t.w, a0.w);
            }
        }
        if (sl1) {
            float cnt = (float)__popc(sl1);
            float xc = g_xbn[(size_t)n1 * CC + lane];
            float4 t = make_float4(0.f, 0.f, 0.f, 0.f);
#pragma unroll
            for (int c = 0; c < CC; c++) {
                float xb = __shfl_sync(0xffffffffu, xc, c);
                float4 wv = sW04[c * 8 + q];
                t.x = fmaf(xb, wv.x, t.x); t.y = fmaf(xb, wv.y, t.y);
                t.z = fmaf(xb, wv.z, t.z); t.w = fmaf(xb, wv.w, t.w);
            }
            if (gid == 0) {
                a1.x = fmaf(cnt, t.x, a1.x); a1.y = fmaf(cnt, t.y, a1.y);
                a1.z = fmaf(cnt, t.z, a1.z); a1.w = fmaf(cnt, t.w, a1.w);
            }
        }

        // main: 4 edges per step per node, float4 channel loads
#pragma unroll
        for (int i = 0; i < 32; i += 4) {
            unsigned sa0 = __shfl_sync(0xffffffffu, ed0.x, i + gid);
            float    wa0 = __shfl_sync(0xffffffffu, w0v,   i + gid);
            unsigned sa1 = __shfl_sync(0xffffffffu, ed1.x, i + gid);
            float    wa1 = __shfl_sync(0xffffffffu, w1v,   i + gid);
            float4 v0 = Y4[(size_t)sa0 * 8 + q];
            float4 v1 = Y4[(size_t)sa1 * 8 + q];
            a0.x = fmaf(wa0, v0.x, a0.x); a0.y = fmaf(wa0, v0.y, a0.y);
            a0.z = fmaf(wa0, v0.z, a0.z); a0.w = fmaf(wa0, v0.w, a0.w);
            a1.x = fmaf(wa1, v1.x, a1.x); a1.y = fmaf(wa1, v1.y, a1.y);
            a1.z = fmaf(wa1, v1.z, a1.z); a1.w = fmaf(wa1, v1.w, a1.w);
        }
        if (j0 < e0) j0 += 32;
        if (j1 < e1) j1 += 32;
    }

    // reduce across the 4 groups (lanes q, q+8, q+16, q+24)
#pragma unroll
    for (int o = 8; o <= 16; o <<= 1) {
        a0.x += __shfl_xor_sync(0xffffffffu, a0.x, o);
        a0.y += __shfl_xor_sync(0xffffffffu, a0.y, o);
        a0.z += __shfl_xor_sync(0xffffffffu, a0.z, o);
        a0.w += __shfl_xor_sync(0xffffffffu, a0.w, o);
        a1.x += __shfl_xor_sync(0xffffffffu, a1.x, o);
        a1.y += __shfl_xor_sync(0xffffffffu, a1.y, o);
        a1.z += __shfl_xor_sync(0xffffffffu, a1.z, o);
        a1.w += __shfl_xor_sync(0xffffffffu, a1.w, o);
    }
    o0 = make_float4(fmaxf(a0.x, 0.f), fmaxf(a0.y, 0.f),
                     fmaxf(a0.z, 0.f), fmaxf(a0.w, 0.f));
    o1 = make_float4(fmaxf(a1.x, 0.f), fmaxf(a1.y, 0.f),
                     fmaxf(a1.z, 0.f), fmaxf(a1.w, 0.f));
}

// ---------------------------------------------------------------------------
// Kernel 4: fused pipelined CSR gather + fc1 GEMV + head + cleanup
// 128-thread blocks, 4 CTAs/SM; 8-node tiles; float4 group-gather.
// ---------------------------------------------------------------------------
__global__ __launch_bounds__(FBLK, 4)
void fused_kernel(const float* __restrict__ W,       // W[0] block for self-loops
                  const float* __restrict__ fc1_w,
                  const float* __restrict__ fc1_b,
                  const float* __restrict__ fc2_w,
                  const float* __restrict__ fc2_b,
                  float* __restrict__ out) {
    __shared__ __align__(16) float sW0[CC * HH];
    __shared__ __align__(16) float sres[2][256];     // 8 nodes x 32 per buffer
    __shared__ float sAcc[FC];
    for (int i = threadIdx.x; i < CC * HH; i += FBLK) sW0[i] = W[i];

    // zero histogram for the NEXT replay (cnt already consumed by scan)
    for (int idx = blockIdx.x * FBLK + threadIdx.x; idx < CNTSZ; idx += FGRID * FBLK)
        g_cnt[idx] = 0u;
    __syncthreads();

    const int tid  = threadIdx.x;
    const int w    = tid >> 5;        // warp 0..3
    const int lane = tid & 31;
    const int q    = lane & 7;
    const int nbeg = blockIdx.x * NPB;
    const int nend = min(nbeg + NPB, NN);
    const int nt   = (nend - nbeg + 7) >> 3;   // 8-node tiles

    const float4* sW04 = reinterpret_cast<const float4*>(sW0);

    float acc[16];
#pragma unroll
    for (int k = 0; k < 16; k++) acc[k] = 0.f;

    const float4* W4 = reinterpret_cast<const float4*>(fc1_w);

    // prologue: gather tile 0 (warp w: nodes w and w+4)
    {
        float4 r0, r1;
        gather2_f4(nbeg + w, nbeg + 4 + w, nend, sW04, r0, r1);
        float4* S4 = reinterpret_cast<float4*>(sres[0]);
        if (lane < 8) {
            S4[w * 8 + q]       = r0;
            S4[(w + 4) * 8 + q] = r1;
        }
    }
    __syncthreads();

    for (int t = 0; t < nt; t++) {
        int cur = t & 1;
        // gather tile t+1 FIRST (loads in flight while gemv streams)
        float4 rn0 = make_float4(0.f, 0.f, 0.f, 0.f);
        float4 rn1 = make_float4(0.f, 0.f, 0.f, 0.f);
        if (t + 1 < nt) {
            int b = nbeg + (t + 1) * 8;
            gather2_f4(b + w, b + 4 + w, nend, sW04, rn0, rn1);
        }

        // gemv over tile t: warp w owns f-range [w*16, w*16+16); 2 slot passes
        int t0 = nbeg + t * 8;
        int nv4 = (min(t0 + 8, nend) - t0) * 8;     // valid float4 slots (<=64)
        const float4* R4 = reinterpret_cast<const float4*>(sres[cur]);
#pragma unroll
        for (int p = 0; p < 2; p++) {
            int slot = lane + p * 32;
            if (slot < nv4) {
                float4 rv = R4[slot];
                size_t base = (size_t)t0 * 8 + slot;
#pragma unroll
                for (int k = 0; k < 16; k++) {
                    int f = w * 16 + k;
                    float4 wv = __ldcs(W4 + (size_t)f * NH4 + base);
                    acc[k] = fmaf(rv.x, wv.x, acc[k]);
                    acc[k] = fmaf(rv.y, wv.y, acc[k]);
                    acc[k] = fmaf(rv.z, wv.z, acc[k]);
                    acc[k] = fmaf(rv.w, wv.w, acc[k]);
                }
            }
        }
        {
            float4* S4 = reinterpret_cast<float4*>(sres[1 - cur]);
            if (lane < 8) {
                S4[w * 8 + q]       = rn0;
                S4[(w + 4) * 8 + q] = rn1;
            }
        }
        __syncthreads();
    }

    // reduction: warp w exclusively owns f-range [w*16, w*16+16)
#pragma unroll
    for (int k = 0; k < 16; k++) {
        float v = acc[k];
        v += __shfl_xor_sync(0xffffffffu, v, 16);
        v += __shfl_xor_sync(0xffffffffu, v, 8);
        v += __shfl_xor_sync(0xffffffffu, v, 4);
        v += __shfl_xor_sync(0xffffffffu, v, 2);
        v += __shfl_xor_sync(0xffffffffu, v, 1);
        if (lane == 0) sAcc[w * 16 + k] = v;
    }
    __syncthreads();
    if (tid < FC) atomicAdd(&g_hacc[tid], sAcc[tid]);
    __syncthreads();

    // last block: head + cleanup
    __shared__ bool isLast;
    if (tid == 0) {
        __threadfence();
        isLast = (atomicAdd(&g_sem, 1u) == (unsigned)(FGRID - 1));
    }
    __syncthreads();
    if (isLast) {
        __threadfence();
        __shared__ float hv[FC];
        volatile float* vh = g_hacc;
        if (tid < FC) hv[tid] = fmaxf(vh[tid] + fc1_b[tid], 0.f);
        __syncthreads();
        if (tid < NCLS) {
            float s = fc2_b[tid];
#pragma unroll
            for (int f = 0; f < FC; f++)
                s = fmaf(hv[f], fc2_w[tid * FC + f], s);
            out[tid] = s;
        }
        __syncthreads();
        if (tid < FC) g_hacc[tid] = 0.f;
        if (tid == 0) g_sem = 0u;
    }
}

// ---------------------------------------------------------------------------
// launch
// ---------------------------------------------------------------------------
extern "C" void kernel_launch(void* const* d_in, const int* in_sizes, int n_in,
                              void* d_out, int out_size) {
    const float* x        = (const float*)d_in[0];
    const float* ew       = (const float*)d_in[1];
    const float* W        = (const float*)d_in[2];
    const float* bn_gamma = (const float*)d_in[3];
    const float* bn_beta  = (const float*)d_in[4];
    const float* bn_mean  = (const float*)d_in[5];
    const float* bn_var   = (const float*)d_in[6];
    const float* fc1_w    = (const float*)d_in[7];
    const float* fc1_b    = (const float*)d_in[8];
    const float* fc2_w    = (const float*)d_in[9];
    const float* fc2_b    = (const float*)d_in[10];
    const int*   ei       = (const int*)d_in[11];
    float* out            = (float*)d_out;

    prep_kernel<<<(NN * CC) / 256, 256>>>(x, bn_gamma, bn_beta, bn_mean, bn_var, W, ei);
    scan_kernel<<<TILES, 256>>>();
    reorder_kernel<<<(QE + 255) / 256, 256>>>(ei, ew);
    fused_kernel<<<FGRID, FBLK>>>(W, fc1_w, fc1_b, fc2_w, fc2_b, out);
}